// round 8
// baseline (speedup 1.0000x reference)
#include <cuda_runtime.h>
#include <cuda_bf16.h>
#include <cstdint>

#define N_NODES 100000
#define F1 128
#define F2 64
#define EMAX 1600000

// Scratch (device globals: allocation-free, graph-safe)
__device__ float g_bufA[N_NODES * F2];   // GEMM output (pre-aggregation messages)
__device__ float g_bufC[N_NODES * F2];   // hidden activations h1
__device__ float g_rso[N_NODES];         // rsqrt(deg_out)
__device__ float g_rsi[N_NODES];         // rsqrt(deg_in)
__device__ int   g_dego[N_NODES];
__device__ int   g_degi[N_NODES];
__device__ int   g_off[N_NODES];         // segment start per dst node
__device__ int   g_cur[N_NODES];         // fill cursor per dst node
__device__ int   g_sorted[EMAX];         // src indices grouped by dst
__device__ int   g_total;                // segment allocator

// ---------------------------------------------------------------------------
__global__ void k_zero() {
    int i = blockIdx.x * blockDim.x + threadIdx.x;
    if (i < N_NODES) { g_dego[i] = 0; g_degi[i] = 0; }
    if (i == 0) g_total = 0;
}

__global__ void k_degree(const int* __restrict__ src, const int* __restrict__ dst, int E) {
    int i = blockIdx.x * blockDim.x + threadIdx.x;
    if (i >= E) return;
    atomicAdd(&g_dego[src[i]], 1);
    atomicAdd(&g_degi[dst[i]], 1);
}

// Segment allocation (warp scan + 1 atomic/warp) fused with norm computation.
__global__ void k_alloc() {
    int i = blockIdx.x * blockDim.x + threadIdx.x;
    int lane = threadIdx.x & 31;
    int deg = 0, dego = 0;
    if (i < N_NODES) { deg = g_degi[i]; dego = g_dego[i]; }
    int incl = deg;
#pragma unroll
    for (int o = 1; o < 32; o <<= 1) {
        int n = __shfl_up_sync(0xFFFFFFFFu, incl, o);
        if (lane >= o) incl += n;
    }
    int wtotal = __shfl_sync(0xFFFFFFFFu, incl, 31);
    int base = 0;
    if (lane == 0) base = atomicAdd(&g_total, wtotal);
    base = __shfl_sync(0xFFFFFFFFu, base, 0);
    if (i < N_NODES) {
        int off = base + incl - deg;
        g_off[i] = off;
        g_cur[i] = off;
        g_rsi[i] = rsqrtf((float)max(deg, 1));
        g_rso[i] = rsqrtf((float)max(dego, 1));
    }
}

// Group src indices by dst (counting-sort placement).
__global__ void k_bin(const int* __restrict__ src, const int* __restrict__ dst, int E) {
    int e = blockIdx.x * blockDim.x + threadIdx.x;
    if (e >= E) return;
    int d = dst[e];
    int p = atomicAdd(&g_cur[d], 1);
    g_sorted[p] = src[e];
}

// ---------------------------------------------------------------------------
// Tensor-core GEMM:  Y[r,:] = (X[r,:] @ W) * g_rso[r]
// mma.sync.m16n8k8 tf32 with hi/lo split (hi*hi + hi*lo + lo*hi) for fp32-
// equivalent precision. 128-row tile, 8 warps x 16 rows. Smem rows padded +4
// floats so all fragment LDS are bank-conflict-free (bank = 4*g + t).
__device__ __forceinline__ uint32_t f2tf32(float f) {
    uint32_t r;
    asm("cvt.rna.tf32.f32 %0, %1;" : "=r"(r) : "f"(f));
    return r;
}

__device__ __forceinline__ void mma_tf32(float acc[4],
                                         uint32_t a0, uint32_t a1, uint32_t a2, uint32_t a3,
                                         uint32_t b0, uint32_t b1) {
    asm volatile(
        "mma.sync.aligned.m16n8k8.row.col.f32.tf32.tf32.f32 "
        "{%0,%1,%2,%3}, {%4,%5,%6,%7}, {%8,%9}, {%0,%1,%2,%3};"
        : "+f"(acc[0]), "+f"(acc[1]), "+f"(acc[2]), "+f"(acc[3])
        : "r"(a0), "r"(a1), "r"(a2), "r"(a3), "r"(b0), "r"(b1));
}

template <int K>
__global__ void __launch_bounds__(256)
k_gemm_mma(const float* __restrict__ X, const float* __restrict__ W,
           float* __restrict__ Y, int M) {
    constexpr int KP = K + 4;                 // padded row stride (floats)
    extern __shared__ float smem[];
    float* sX   = smem;                       // [128][KP] fp32
    float* sWhi = sX + 128 * KP;              // [64][KP]  (n-major, tf32-hi)
    float* sWlo = sWhi + 64 * KP;             // [64][KP]  (n-major, tf32-lo)

    const int tid = threadIdx.x;
    const int row0 = blockIdx.x * 128;

    // W [K][64] (k-major) -> transposed n-major hi/lo in smem
    for (int i = tid; i < K * 64; i += 256) {
        int k = i >> 6, n = i & 63;
        float w = __ldg(W + i);
        float hi = __uint_as_float(f2tf32(w));
        sWhi[n * KP + k] = hi;
        sWlo[n * KP + k] = w - hi;
    }
    // X tile [128][K] (zero-fill OOB rows)
    for (int i = tid; i < 128 * (K / 4); i += 256) {
        int r = i / (K / 4), c = i % (K / 4);
        float4 v = make_float4(0.f, 0.f, 0.f, 0.f);
        if (row0 + r < M)
            v = __ldg(((const float4*)(X + (size_t)(row0 + r) * K)) + c);
        *(float4*)(sX + r * KP + c * 4) = v;
    }
    __syncthreads();

    const int wid = tid >> 5, lane = tid & 31;
    const int r0 = wid * 16;          // warp row offset within tile
    const int g = lane >> 2, t = lane & 3;

    float acc[8][4];
#pragma unroll
    for (int j = 0; j < 8; j++)
#pragma unroll
        for (int c = 0; c < 4; c++) acc[j][c] = 0.0f;

    for (int k0 = 0; k0 < K; k0 += 8) {
        // A fragment (rows r0+g / r0+g+8, cols k0+t / k0+t+4), split hi/lo
        float af0 = sX[(r0 + g    ) * KP + k0 + t    ];
        float af1 = sX[(r0 + g + 8) * KP + k0 + t    ];
        float af2 = sX[(r0 + g    ) * KP + k0 + t + 4];
        float af3 = sX[(r0 + g + 8) * KP + k0 + t + 4];
        uint32_t ah0 = f2tf32(af0), ah1 = f2tf32(af1), ah2 = f2tf32(af2), ah3 = f2tf32(af3);
        uint32_t al0 = f2tf32(af0 - __uint_as_float(ah0));
        uint32_t al1 = f2tf32(af1 - __uint_as_float(ah1));
        uint32_t al2 = f2tf32(af2 - __uint_as_float(ah2));
        uint32_t al3 = f2tf32(af3 - __uint_as_float(ah3));

#pragma unroll
        for (int j = 0; j < 8; j++) {
            const float* whp = sWhi + (j * 8 + g) * KP + k0;
            const float* wlp = sWlo + (j * 8 + g) * KP + k0;
            uint32_t bh0 = __float_as_uint(whp[t]);
            uint32_t bh1 = __float_as_uint(whp[t + 4]);
            uint32_t bl0 = __float_as_uint(wlp[t]);
            uint32_t bl1 = __float_as_uint(wlp[t + 4]);
            mma_tf32(acc[j], ah0, ah1, ah2, ah3, bh0, bh1);   // hi*hi
            mma_tf32(acc[j], ah0, ah1, ah2, ah3, bl0, bl1);   // hi*lo
            mma_tf32(acc[j], al0, al1, al2, al3, bh0, bh1);   // lo*hi
        }
    }

    // Epilogue: scale by rso, store. C map: c0/c1 -> (g, 2t/2t+1), c2/c3 -> (g+8, ...)
    int gr0 = row0 + r0 + g;
    int gr1 = gr0 + 8;
    float s0 = (gr0 < M) ? g_rso[gr0] : 0.f;
    float s1 = (gr1 < M) ? g_rso[gr1] : 0.f;
#pragma unroll
    for (int j = 0; j < 8; j++) {
        int col = j * 8 + 2 * t;
        if (gr0 < M)
            *(float2*)(Y + (size_t)gr0 * 64 + col) = make_float2(acc[j][0] * s0, acc[j][1] * s0);
        if (gr1 < M)
            *(float2*)(Y + (size_t)gr1 * 64 + col) = make_float2(acc[j][2] * s1, acc[j][3] * s1);
    }
}

// ---------------------------------------------------------------------------
// Gather-aggregate per dst node (no atomics), fused epilogue:
//   out[n] = act( rsi[n] * sum_{s in seg(n)} A[s] + bias )
template <bool RELU>
__global__ void k_agg(const float* __restrict__ Asrc, const float* __restrict__ bias,
                      float* __restrict__ out) {
    int idx = blockIdx.x * blockDim.x + threadIdx.x;
    if (idx >= N_NODES * 16) return;
    int node = idx >> 4;
    int c = idx & 15;

    int base = g_off[node];
    int deg  = g_degi[node];
    int end  = base + deg;

    const float4* A = (const float4*)Asrc;
    float4 acc = make_float4(0.f, 0.f, 0.f, 0.f);

    int i = base;
    for (; i + 4 <= end; i += 4) {
        int s0 = __ldg(g_sorted + i);
        int s1 = __ldg(g_sorted + i + 1);
        int s2 = __ldg(g_sorted + i + 2);
        int s3 = __ldg(g_sorted + i + 3);
        float4 v0 = __ldg(A + (size_t)s0 * 16 + c);
        float4 v1 = __ldg(A + (size_t)s1 * 16 + c);
        float4 v2 = __ldg(A + (size_t)s2 * 16 + c);
        float4 v3 = __ldg(A + (size_t)s3 * 16 + c);
        acc.x += (v0.x + v1.x) + (v2.x + v3.x);
        acc.y += (v0.y + v1.y) + (v2.y + v3.y);
        acc.z += (v0.z + v1.z) + (v2.z + v3.z);
        acc.w += (v0.w + v1.w) + (v2.w + v3.w);
    }
    for (; i < end; ++i) {
        int s = __ldg(g_sorted + i);
        float4 v = __ldg(A + (size_t)s * 16 + c);
        acc.x += v.x; acc.y += v.y; acc.z += v.z; acc.w += v.w;
    }

    float sc = g_rsi[node];
    float4 bb = __ldg(((const float4*)bias) + c);
    float4 o;
    o.x = acc.x * sc + bb.x;
    o.y = acc.y * sc + bb.y;
    o.z = acc.z * sc + bb.z;
    o.w = acc.w * sc + bb.w;
    if (RELU) {
        o.x = fmaxf(o.x, 0.f); o.y = fmaxf(o.y, 0.f);
        o.z = fmaxf(o.z, 0.f); o.w = fmaxf(o.w, 0.f);
    }
    ((float4*)out)[idx] = o;
}

// ---------------------------------------------------------------------------
extern "C" void kernel_launch(void* const* d_in, const int* in_sizes, int n_in,
                              void* d_out, int out_size) {
    const float* x   = (const float*)d_in[0];
    const int*   src = (const int*)  d_in[1];
    const int*   dst = (const int*)  d_in[2];
    const float* W1  = (const float*)d_in[3];
    const float* b1  = (const float*)d_in[4];
    const float* W2  = (const float*)d_in[5];
    const float* b2  = (const float*)d_in[6];
    float* out = (float*)d_out;

    const int E = in_sizes[1];
    const int M = in_sizes[0] / F1;  // == N_NODES

    void* pA = nullptr; void* pC = nullptr;
    cudaGetSymbolAddress(&pA, g_bufA);
    cudaGetSymbolAddress(&pC, g_bufC);

    const int T = 256;
    const int smem1 = (128 * (F1 + 4) + 2 * 64 * (F1 + 4)) * 4;  // ~132 KB
    const int smem2 = (128 * (F2 + 4) + 2 * 64 * (F2 + 4)) * 4;  // ~68 KB
    cudaFuncSetAttribute(k_gemm_mma<F1>, cudaFuncAttributeMaxDynamicSharedMemorySize, smem1);
    cudaFuncSetAttribute(k_gemm_mma<F2>, cudaFuncAttributeMaxDynamicSharedMemorySize, smem2);

    // 1) zero degrees + allocator
    k_zero<<<(N_NODES + T - 1) / T, T>>>();
    // 2) degrees
    k_degree<<<(E + T - 1) / T, T>>>(src, dst, E);
    // 3) segment allocation + norms
    k_alloc<<<(N_NODES + T - 1) / T, T>>>();
    // 4) group src by dst
    k_bin<<<(E + T - 1) / T, T>>>(src, dst, E);
    // 5) layer-1 GEMM (tensor): A = (x @ W1) * rso
    k_gemm_mma<F1><<<(M + 127) / 128, 256, smem1>>>(x, W1, (float*)pA, M);
    // 6) h1 = relu(rsi * sum A[srcs] + b1)
    k_agg<true><<<(N_NODES * 16 + T - 1) / T, T>>>((const float*)pA, b1, (float*)pC);
    // 7) layer-2 GEMM (tensor): A = (h1 @ W2) * rso
    k_gemm_mma<F2><<<(M + 127) / 128, 256, smem2>>>((const float*)pC, W2, (float*)pA, M);
    // 8) out = rsi * sum A[srcs] + b2
    k_agg<false><<<(N_NODES * 16 + T - 1) / T, T>>>((const float*)pA, b2, out);
}

// round 9
// speedup vs baseline: 1.1172x; 1.1172x over previous
#include <cuda_runtime.h>
#include <cuda_bf16.h>
#include <cstdint>

#define N_NODES 100000
#define F1 128
#define F2 64
#define EMAX 1600000

// Scratch (device globals: allocation-free, graph-safe)
__device__ float g_bufA[N_NODES * F2];   // GEMM output (pre-aggregation messages)
__device__ float g_bufC[N_NODES * F2];   // hidden activations h1
__device__ float g_rso[N_NODES];         // rsqrt(deg_out)
__device__ float g_rsi[N_NODES];         // rsqrt(deg_in)
__device__ int   g_dego[N_NODES];
__device__ int   g_degi[N_NODES];
__device__ int   g_off[N_NODES];         // segment start per dst node
__device__ int   g_cur[N_NODES];         // fill cursor per dst node
__device__ int   g_sorted[EMAX];         // src indices grouped by dst
__device__ int   g_total;                // segment allocator

// ---------------------------------------------------------------------------
__global__ void k_zero() {
    int i = blockIdx.x * blockDim.x + threadIdx.x;
    if (i < N_NODES) { g_dego[i] = 0; g_degi[i] = 0; }
    if (i == 0) g_total = 0;
}

__global__ void k_degree(const int* __restrict__ src, const int* __restrict__ dst, int E) {
    int i = blockIdx.x * blockDim.x + threadIdx.x;
    if (i >= E) return;
    atomicAdd(&g_dego[src[i]], 1);
    atomicAdd(&g_degi[dst[i]], 1);
}

// Segment allocation (warp scan + 1 atomic/warp) fused with norm computation.
__global__ void k_alloc() {
    int i = blockIdx.x * blockDim.x + threadIdx.x;
    int lane = threadIdx.x & 31;
    int deg = 0, dego = 0;
    if (i < N_NODES) { deg = g_degi[i]; dego = g_dego[i]; }
    int incl = deg;
#pragma unroll
    for (int o = 1; o < 32; o <<= 1) {
        int n = __shfl_up_sync(0xFFFFFFFFu, incl, o);
        if (lane >= o) incl += n;
    }
    int wtotal = __shfl_sync(0xFFFFFFFFu, incl, 31);
    int base = 0;
    if (lane == 0) base = atomicAdd(&g_total, wtotal);
    base = __shfl_sync(0xFFFFFFFFu, base, 0);
    if (i < N_NODES) {
        int off = base + incl - deg;
        g_off[i] = off;
        g_cur[i] = off;
        g_rsi[i] = rsqrtf((float)max(deg, 1));
        g_rso[i] = rsqrtf((float)max(dego, 1));
    }
}

// Group src indices by dst (counting-sort placement).
__global__ void k_bin(const int* __restrict__ src, const int* __restrict__ dst, int E) {
    int e = blockIdx.x * blockDim.x + threadIdx.x;
    if (e >= E) return;
    int d = dst[e];
    int p = atomicAdd(&g_cur[d], 1);
    g_sorted[p] = src[e];
}

// ---------------------------------------------------------------------------
// Y[r, :] = (X[r, :] @ W) * g_rso[r]    X:[M,K]  W:[K,64]  Y:[M,64]
// 128-row tile, 256 threads, 8x4 register blocking. Per k-quad: 128 FFMA vs
// 12 LDS.128 (8 of which are 2-address warp-broadcast) -> FMA-bound.
template <int K>
__global__ void __launch_bounds__(256, 2)
k_gemm_scale(const float* __restrict__ X, const float* __restrict__ W,
             float* __restrict__ Y, int M) {
    extern __shared__ float smem[];
    float* sW = smem;            // [K][64]
    float* sX = smem + K * 64;   // [128][K]

    const int tid = threadIdx.x;
    const int row0 = blockIdx.x * 128;

    // Load W (whole matrix)
    for (int i = tid; i < K * 16; i += 256)
        ((float4*)sW)[i] = ((const float4*)W)[i];

    // Load X tile (zero-fill out-of-range rows)
    const int RV = K / 4;  // float4 per row
    for (int i = tid; i < 128 * RV; i += 256) {
        int r = i / RV, c = i % RV;
        float4 v = make_float4(0.f, 0.f, 0.f, 0.f);
        if (row0 + r < M)
            v = ((const float4*)(X + (size_t)(row0 + r) * K))[c];
        ((float4*)sX)[i] = v;
    }
    __syncthreads();

    const int tx = tid & 15;   // col group (4 cols)
    const int ty = tid >> 4;   // row group (8 rows)

    float acc[8][4];
#pragma unroll
    for (int j = 0; j < 8; j++)
#pragma unroll
        for (int c = 0; c < 4; c++) acc[j][c] = 0.0f;

    for (int k4 = 0; k4 < K / 4; ++k4) {
        float4 xv[8];
#pragma unroll
        for (int j = 0; j < 8; j++)
            xv[j] = ((const float4*)(sX + (ty * 8 + j) * K))[k4];
#pragma unroll
        for (int kk = 0; kk < 4; kk++) {
            float4 wv = ((const float4*)(sW + (k4 * 4 + kk) * 64))[tx];
#pragma unroll
            for (int j = 0; j < 8; j++) {
                const float* xp = (const float*)&xv[j];
                float xs = xp[kk];
                acc[j][0] += xs * wv.x;
                acc[j][1] += xs * wv.y;
                acc[j][2] += xs * wv.z;
                acc[j][3] += xs * wv.w;
            }
        }
    }

#pragma unroll
    for (int j = 0; j < 8; j++) {
        int gr = row0 + ty * 8 + j;
        if (gr < M) {
            float s = g_rso[gr];
            float4 o = make_float4(acc[j][0] * s, acc[j][1] * s, acc[j][2] * s, acc[j][3] * s);
            ((float4*)(Y + (size_t)gr * 64))[tx] = o;
        }
    }
}

// ---------------------------------------------------------------------------
// Gather-aggregate per dst node (no atomics), fused epilogue:
//   out[n] = act( rsi[n] * sum_{s in seg(n)} A[s] + bias )
template <bool RELU>
__global__ void k_agg(const float* __restrict__ Asrc, const float* __restrict__ bias,
                      float* __restrict__ out) {
    int idx = blockIdx.x * blockDim.x + threadIdx.x;
    if (idx >= N_NODES * 16) return;
    int node = idx >> 4;
    int c = idx & 15;

    int base = g_off[node];
    int deg  = g_degi[node];
    int end  = base + deg;

    const float4* A = (const float4*)Asrc;
    float4 acc = make_float4(0.f, 0.f, 0.f, 0.f);

    int i = base;
    for (; i + 4 <= end; i += 4) {
        int s0 = __ldg(g_sorted + i);
        int s1 = __ldg(g_sorted + i + 1);
        int s2 = __ldg(g_sorted + i + 2);
        int s3 = __ldg(g_sorted + i + 3);
        float4 v0 = __ldg(A + (size_t)s0 * 16 + c);
        float4 v1 = __ldg(A + (size_t)s1 * 16 + c);
        float4 v2 = __ldg(A + (size_t)s2 * 16 + c);
        float4 v3 = __ldg(A + (size_t)s3 * 16 + c);
        acc.x += (v0.x + v1.x) + (v2.x + v3.x);
        acc.y += (v0.y + v1.y) + (v2.y + v3.y);
        acc.z += (v0.z + v1.z) + (v2.z + v3.z);
        acc.w += (v0.w + v1.w) + (v2.w + v3.w);
    }
    for (; i < end; ++i) {
        int s = __ldg(g_sorted + i);
        float4 v = __ldg(A + (size_t)s * 16 + c);
        acc.x += v.x; acc.y += v.y; acc.z += v.z; acc.w += v.w;
    }

    float sc = g_rsi[node];
    float4 bb = __ldg(((const float4*)bias) + c);
    float4 o;
    o.x = acc.x * sc + bb.x;
    o.y = acc.y * sc + bb.y;
    o.z = acc.z * sc + bb.z;
    o.w = acc.w * sc + bb.w;
    if (RELU) {
        o.x = fmaxf(o.x, 0.f); o.y = fmaxf(o.y, 0.f);
        o.z = fmaxf(o.z, 0.f); o.w = fmaxf(o.w, 0.f);
    }
    ((float4*)out)[idx] = o;
}

// ---------------------------------------------------------------------------
extern "C" void kernel_launch(void* const* d_in, const int* in_sizes, int n_in,
                              void* d_out, int out_size) {
    const float* x   = (const float*)d_in[0];
    const int*   src = (const int*)  d_in[1];
    const int*   dst = (const int*)  d_in[2];
    const float* W1  = (const float*)d_in[3];
    const float* b1  = (const float*)d_in[4];
    const float* W2  = (const float*)d_in[5];
    const float* b2  = (const float*)d_in[6];
    float* out = (float*)d_out;

    const int E = in_sizes[1];
    const int M = in_sizes[0] / F1;  // == N_NODES

    void* pA = nullptr; void* pC = nullptr;
    cudaGetSymbolAddress(&pA, g_bufA);
    cudaGetSymbolAddress(&pC, g_bufC);

    const int T = 256;
    const int smem1 = (F1 * 64 + 128 * F1) * 4;  // 96 KB
    const int smem2 = (F2 * 64 + 128 * F2) * 4;  // 48 KB
    cudaFuncSetAttribute(k_gemm_scale<F1>, cudaFuncAttributeMaxDynamicSharedMemorySize, smem1);
    cudaFuncSetAttribute(k_gemm_scale<F2>, cudaFuncAttributeMaxDynamicSharedMemorySize, smem2);

    // 1) zero int degrees + allocator
    k_zero<<<(N_NODES + T - 1) / T, T>>>();
    // 2) integer degrees
    k_degree<<<(E + T - 1) / T, T>>>(src, dst, E);
    // 3) per-node segment allocation + rsqrt norms (fused)
    k_alloc<<<(N_NODES + T - 1) / T, T>>>();
    // 4) group src indices by dst (counting sort placement)
    k_bin<<<(E + T - 1) / T, T>>>(src, dst, E);
    // 5) layer 1 GEMM first (64-wide messages): A = (x @ W1) * rso
    k_gemm_scale<F1><<<(M + 127) / 128, 256, smem1>>>(x, W1, (float*)pA, M);
    // 6) gather-aggregate + epilogue: h1 = relu(rsi * sum A[srcs] + b1)
    k_agg<true><<<(N_NODES * 16 + T - 1) / T, T>>>((const float*)pA, b1, (float*)pC);
    // 7) layer 2 GEMM: A = (h1 @ W2) * rso
    k_gemm_scale<F2><<<(M + 127) / 128, 256, smem2>>>((const float*)pC, W2, (float*)pA, M);
    // 8) gather-aggregate + epilogue: out = rsi * sum A[srcs] + b2
    k_agg<false><<<(N_NODES * 16 + T - 1) / T, T>>>((const float*)pA, b2, out);
}